// round 2
// baseline (speedup 1.0000x reference)
#include <cuda_runtime.h>
#include <cstdint>

#define BB   256
#define CTXD 512
#define DOF  6
#define WSZ  300
#define JZ   306          // DOF + WSZ
#define PG   256
#define PW   512
#define HG   256
#define HW   512
#define NL   2
#define MS   20
#define STEPS 19
#define GOFF (BB*MS*DOF)  // offset of ws in out (30720)

// ---------------- scratch (device globals: no allocs allowed) ----------------
__device__ float d_Mg[(size_t)BB*PG*DOF];          // 1.5 MB
__device__ float d_Mw[(size_t)BB*PW*JZ];           // 160 MB
__device__ float d_xpre[BB*PG];
__device__ float d_ypre[BB*PW];
__device__ float d_xg[BB*PG];
__device__ float d_yw[BB*PW];
__device__ float d_gh[NL*BB*HG];
__device__ float d_gc[NL*BB*HG];
__device__ float d_wh[NL*BB*HW];
__device__ float d_wc[NL*BB*HW];
__device__ float d_gates_g[BB*4*HG];
__device__ float d_gates_w[BB*4*HW];
__device__ float d_bias_g[NL*4*HG];
__device__ float d_bias_w[NL*4*HW];

__device__ __forceinline__ float sigmoidf_(float x) { return 1.0f / (1.0f + expf(-x)); }

// ---------------- init: zero states, combine biases, write t=0 rows ----------
__global__ void init_kernel(const float* __restrict__ g0, const float* __restrict__ w0,
                            const float* __restrict__ lg_bih, const float* __restrict__ lg_bhh,
                            const float* __restrict__ lw_bih, const float* __restrict__ lw_bhh,
                            float* __restrict__ out)
{
    int tid = blockIdx.x * blockDim.x + threadIdx.x;
    int nt  = gridDim.x * blockDim.x;
    for (int i = tid; i < NL*BB*HG; i += nt) { d_gh[i] = 0.f; d_gc[i] = 0.f; }
    for (int i = tid; i < NL*BB*HW; i += nt) { d_wh[i] = 0.f; d_wc[i] = 0.f; }
    for (int i = tid; i < NL*4*HG; i += nt) d_bias_g[i] = lg_bih[i] + lg_bhh[i];
    for (int i = tid; i < NL*4*HW; i += nt) d_bias_w[i] = lw_bih[i] + lw_bhh[i];
    for (int i = tid; i < BB*DOF; i += nt) {
        int b = i / DOF, j = i % DOF;
        out[b*(MS*DOF) + j] = g0[i];
    }
    for (int i = tid; i < BB*WSZ; i += nt) {
        int b = i / WSZ, j = i % WSZ;
        out[GOFF + b*(MS*WSZ) + j] = w0[i];
    }
}

// ---------------- precompute M_g: per-o block, per-b thread ------------------
__global__ void pre_Mg_kernel(const float* __restrict__ ctx, const float* __restrict__ bgW)
{
    int o = blockIdx.x;                 // 0..PG-1
    __shared__ float w[CTXD*DOF];       // 12 KB
    for (int i = threadIdx.x; i < CTXD*DOF; i += blockDim.x)
        w[i] = bgW[(size_t)o*CTXD*DOF + i];
    __syncthreads();
    int b = threadIdx.x;                // blockDim = 256 = BB
    const float* cr = ctx + (size_t)b*CTXD;
    float acc[DOF]; 
    #pragma unroll
    for (int j = 0; j < DOF; j++) acc[j] = 0.f;
    for (int i = 0; i < CTXD; i++) {
        float c = cr[i];
        #pragma unroll
        for (int j = 0; j < DOF; j++) acc[j] += c * w[i*DOF + j];
    }
    #pragma unroll
    for (int j = 0; j < DOF; j++)
        d_Mg[((size_t)b*PG + o)*DOF + j] = acc[j];
}

// ---------------- generic fp32 GEMM (NT or NN), dual-pair, bias, tanh --------
// C[m,n] = sum_k A[m,k]*Bsel(k,n) (+ A2*B2) (+bias) (tanh?) with n-bounds guards.
// transB=1: B is N x K row-major (NT).  transB=0: B is K x N row-major (NN).
// batch via blockIdx.z: B += z*strideB, C += z*strideC.
__global__ void __launch_bounds__(256)
gemm_kernel(const float* __restrict__ A, int lda,
            const float* __restrict__ B, int ldb, int transB,
            const float* __restrict__ A2, int lda2,
            const float* __restrict__ B2, int ldb2,
            const float* __restrict__ bias,
            float* __restrict__ C, int ldc,
            int M, int N, int K, int K2, int act,
            long long strideB, long long strideC)
{
    B += (long long)blockIdx.z * strideB;
    C += (long long)blockIdx.z * strideC;

    const int bm = blockIdx.y * 64;
    const int bn = blockIdx.x * 64;
    __shared__ float sA[16][68];
    __shared__ float sB[16][68];

    const int tx = threadIdx.x & 15;
    const int ty = threadIdx.x >> 4;
    float acc[4][4];
    #pragma unroll
    for (int i = 0; i < 4; i++)
        #pragma unroll
        for (int j = 0; j < 4; j++) acc[i][j] = 0.f;

    for (int pass = 0; pass < 2; ++pass) {
        const float* Ap = pass ? A2 : A;
        const float* Bp = pass ? B2 : B;
        const int ldA = pass ? lda2 : lda;
        const int ldB = pass ? ldb2 : ldb;
        const int Kp  = pass ? K2 : K;
        if (Ap == nullptr || Kp <= 0) continue;

        for (int k0 = 0; k0 < Kp; k0 += 16) {
            // A tile: 64 rows x 16 k, transposed into sA[k][m]
            {
                int r = threadIdx.x >> 2;
                int c = (threadIdx.x & 3) << 2;
                const float4 v = *(const float4*)(Ap + (size_t)(bm + r)*ldA + k0 + c);
                sA[c+0][r] = v.x; sA[c+1][r] = v.y; sA[c+2][r] = v.z; sA[c+3][r] = v.w;
            }
            // B tile into sB[k][n]
            if (transB) {
                int r = threadIdx.x >> 2;          // n index within tile
                int c = (threadIdx.x & 3) << 2;    // k offset
                int n = bn + r;
                float4 v = make_float4(0.f, 0.f, 0.f, 0.f);
                if (n < N) v = *(const float4*)(Bp + (size_t)n*ldB + k0 + c);
                sB[c+0][r] = v.x; sB[c+1][r] = v.y; sB[c+2][r] = v.z; sB[c+3][r] = v.w;
            } else {
                int kk = threadIdx.x >> 4;         // 0..15
                int n4 = (threadIdx.x & 15) << 2;  // 0..60
                const float* src = Bp + (size_t)(k0 + kk)*ldB + bn + n4;
                #pragma unroll
                for (int u = 0; u < 4; u++)
                    sB[kk][n4 + u] = (bn + n4 + u < N) ? src[u] : 0.f;
            }
            __syncthreads();
            #pragma unroll
            for (int kk = 0; kk < 16; kk++) {
                float a0 = sA[kk][ty], a1 = sA[kk][ty+16], a2 = sA[kk][ty+32], a3 = sA[kk][ty+48];
                float b0 = sB[kk][tx], b1 = sB[kk][tx+16], b2 = sB[kk][tx+32], b3 = sB[kk][tx+48];
                acc[0][0] += a0*b0; acc[0][1] += a0*b1; acc[0][2] += a0*b2; acc[0][3] += a0*b3;
                acc[1][0] += a1*b0; acc[1][1] += a1*b1; acc[1][2] += a1*b2; acc[1][3] += a1*b3;
                acc[2][0] += a2*b0; acc[2][1] += a2*b1; acc[2][2] += a2*b2; acc[2][3] += a2*b3;
                acc[3][0] += a3*b0; acc[3][1] += a3*b1; acc[3][2] += a3*b2; acc[3][3] += a3*b3;
            }
            __syncthreads();
        }
    }

    #pragma unroll
    for (int i = 0; i < 4; i++) {
        int m = bm + ty + 16*i;
        #pragma unroll
        for (int j = 0; j < 4; j++) {
            int n = bn + tx + 16*j;
            if (n < N) {
                float v = acc[i][j];
                if (bias) v += bias[n];
                if (act)  v = tanhf(v);
                C[(size_t)m*ldc + n] = v;
            }
        }
    }
}

// ---------------- per-step bilinear matvecs (reads prev outputs from out) ----
__global__ void bilinear_kernel(int t, const float* __restrict__ bg_b,
                                const float* __restrict__ bw_b,
                                const float* __restrict__ out)
{
    int b = blockIdx.x;
    __shared__ float z[JZ];
    int tid = threadIdx.x;
    for (int i = tid; i < JZ; i += blockDim.x) {
        z[i] = (i < DOF) ? out[(size_t)b*MS*DOF + t*DOF + i]
                         : out[GOFF + (size_t)b*MS*WSZ + t*WSZ + (i - DOF)];
    }
    __syncthreads();
    if (blockIdx.y < PW/8) {
        int o = blockIdx.y * 8 + (tid >> 5);
        int lane = tid & 31;
        const float* mw = d_Mw + ((size_t)b*PW + o)*JZ;
        float s = 0.f;
        for (int j = lane; j < JZ; j += 32) s += mw[j] * z[j];
        #pragma unroll
        for (int off = 16; off; off >>= 1) s += __shfl_down_sync(0xffffffffu, s, off);
        if (lane == 0) d_ypre[b*PW + o] = s + bw_b[o];
    } else {
        // x branch: tid is o (256 outputs, 6-elem dot)
        const float* mg = d_Mg + ((size_t)b*PG + tid)*DOF;
        float s = bg_b[tid];
        #pragma unroll
        for (int j = 0; j < DOF; j++) s += mg[j] * z[j];
        d_xpre[b*PG + tid] = s;
    }
}

// ---------------- LSTM pointwise (gate order i,f,g,o) ------------------------
__global__ void lstm_point_kernel(const float* __restrict__ gates,
                                  float* __restrict__ h, float* __restrict__ c, int H)
{
    int idx = blockIdx.x * blockDim.x + threadIdx.x;
    if (idx >= BB*H) return;
    int b = idx / H, j = idx % H;
    const float* g = gates + (size_t)b*4*H;
    float ig = sigmoidf_(g[j]);
    float fg = sigmoidf_(g[H + j]);
    float gg = tanhf(g[2*H + j]);
    float og = sigmoidf_(g[3*H + j]);
    float cn = fg * c[idx] + ig * gg;
    float hn = og * tanhf(cn);
    c[idx] = cn;
    h[idx] = hn;
}

// ---------------- host-side launch helpers -----------------------------------
static inline void launch_gemm(const float* A, int lda, const float* B, int ldb, int transB,
                               const float* A2, int lda2, const float* B2, int ldb2,
                               const float* bias, float* C, int ldc,
                               int M, int N, int K, int K2, int act,
                               long long sB = 0, long long sC = 0, int batch = 1)
{
    dim3 grid((N + 63) / 64, M / 64, batch);
    gemm_kernel<<<grid, 256>>>(A, lda, B, ldb, transB, A2, lda2, B2, ldb2,
                               bias, C, ldc, M, N, K, K2, act, sB, sC);
}

extern "C" void kernel_launch(void* const* d_in, const int* in_sizes, int n_in,
                              void* d_out, int out_size)
{
    const float* ctx    = (const float*)d_in[0];
    const float* goal0  = (const float*)d_in[1];
    const float* w0     = (const float*)d_in[2];
    const float* bg_W   = (const float*)d_in[3];
    const float* bg_b   = (const float*)d_in[4];
    const float* bw_W   = (const float*)d_in[5];
    const float* bw_b   = (const float*)d_in[6];
    const float* fcg_W  = (const float*)d_in[7];
    const float* fcg_b  = (const float*)d_in[8];
    const float* fcw_W  = (const float*)d_in[9];
    const float* fcw_b  = (const float*)d_in[10];
    const float* lg_Wih = (const float*)d_in[11];
    const float* lg_Whh = (const float*)d_in[12];
    const float* lg_bih = (const float*)d_in[13];
    const float* lg_bhh = (const float*)d_in[14];
    const float* lw_Wih = (const float*)d_in[15];
    const float* lw_Whh = (const float*)d_in[16];
    const float* lw_bih = (const float*)d_in[17];
    const float* lw_bhh = (const float*)d_in[18];
    const float* og_W   = (const float*)d_in[19];
    const float* og_b   = (const float*)d_in[20];
    const float* ow_W   = (const float*)d_in[21];
    const float* ow_b   = (const float*)d_in[22];
    float* out = (float*)d_out;

    // --- init + precompute (context is step-invariant) ---
    init_kernel<<<256, 256>>>(goal0, w0, lg_bih, lg_bhh, lw_bih, lw_bhh, out);
    pre_Mg_kernel<<<PG, 256>>>(ctx, bg_W);

    // M_w[b, o, j] = sum_i ctx[b,i] * bw_W[o,i,j] : batched NN GEMM over o
    {
        float* Mw;
        cudaGetSymbolAddress((void**)&Mw, d_Mw);
        launch_gemm(ctx, CTXD, bw_W, JZ, /*transB=*/0,
                    nullptr, 0, nullptr, 0, nullptr,
                    Mw, PW*JZ, BB, JZ, CTXD, 0, /*act=*/0,
                    (long long)CTXD*JZ, (long long)JZ, PW);
    }

    float *xpre, *ypre, *xg, *yw, *gh, *gc, *wh, *wc, *gg_buf, *gw_buf, *bias_g, *bias_w;
    cudaGetSymbolAddress((void**)&xpre, d_xpre);
    cudaGetSymbolAddress((void**)&ypre, d_ypre);
    cudaGetSymbolAddress((void**)&xg, d_xg);
    cudaGetSymbolAddress((void**)&yw, d_yw);
    cudaGetSymbolAddress((void**)&gh, d_gh);
    cudaGetSymbolAddress((void**)&gc, d_gc);
    cudaGetSymbolAddress((void**)&wh, d_wh);
    cudaGetSymbolAddress((void**)&wc, d_wc);
    cudaGetSymbolAddress((void**)&gg_buf, d_gates_g);
    cudaGetSymbolAddress((void**)&gw_buf, d_gates_w);
    cudaGetSymbolAddress((void**)&bias_g, d_bias_g);
    cudaGetSymbolAddress((void**)&bias_w, d_bias_w);

    for (int t = 0; t < STEPS; ++t) {
        // 1. bilinear matvecs
        bilinear_kernel<<<dim3(BB, PW/8 + 1), 256>>>(t, bg_b, bw_b, out);

        // 2. fc + tanh (both branches)
        launch_gemm(xpre, PG, fcg_W, PG, 1, nullptr, 0, nullptr, 0,
                    fcg_b, xg, PG, BB, PG, PG, 0, /*tanh*/1);
        launch_gemm(ypre, PW, fcw_W, PW, 1, nullptr, 0, nullptr, 0,
                    fcw_b, yw, PW, BB, PW, PW, 0, /*tanh*/1);

        // 3. LSTM g (2 layers)
        for (int l = 0; l < NL; ++l) {
            const float* inp = (l == 0) ? xg : gh;           // layer1 input = layer0 h
            launch_gemm(inp, (l == 0) ? PG : HG,
                        lg_Wih + (size_t)l*4*HG*PG, (l == 0) ? PG : HG, 1,
                        gh + (size_t)l*BB*HG, HG,
                        lg_Whh + (size_t)l*4*HG*HG, HG,
                        bias_g + l*4*HG, gg_buf, 4*HG,
                        BB, 4*HG, (l == 0) ? PG : HG, HG, 0);
            lstm_point_kernel<<<(BB*HG + 255)/256, 256>>>(gg_buf, gh + (size_t)l*BB*HG,
                                                          gc + (size_t)l*BB*HG, HG);
        }
        // 4. LSTM w (2 layers)
        for (int l = 0; l < NL; ++l) {
            const float* inp = (l == 0) ? yw : wh;
            launch_gemm(inp, (l == 0) ? PW : HW,
                        lw_Wih + (size_t)l*4*HW*PW, (l == 0) ? PW : HW, 1,
                        wh + (size_t)l*BB*HW, HW,
                        lw_Whh + (size_t)l*4*HW*HW, HW,
                        bias_w + l*4*HW, gw_buf, 4*HW,
                        BB, 4*HW, (l == 0) ? PW : HW, HW, 0);
            lstm_point_kernel<<<(BB*HW + 255)/256, 256>>>(gw_buf, wh + (size_t)l*BB*HW,
                                                          wc + (size_t)l*BB*HW, HW);
        }

        // 5. output projections, written directly into out rows t+1
        launch_gemm(gh + (size_t)1*BB*HG, HG, og_W, HG, 1, nullptr, 0, nullptr, 0,
                    og_b, out + (t + 1)*DOF, MS*DOF, BB, DOF, HG, 0, 0);
        launch_gemm(wh + (size_t)1*BB*HW, HW, ow_W, HW, 1, nullptr, 0, nullptr, 0,
                    ow_b, out + GOFF + (t + 1)*WSZ, MS*WSZ, BB, WSZ, HW, 0, 0);
    }
}

// round 3
// speedup vs baseline: 2.3777x; 2.3777x over previous
#include <cuda_runtime.h>
#include <cstdint>

#define BB   256
#define CTXD 512
#define DOF  6
#define WSZ  300
#define JZ   306          // DOF + WSZ
#define JZP  308          // padded to float4 multiple
#define PG   256
#define PW   512
#define HG   256
#define HW   512
#define NL   2
#define MS   20
#define STEPS 19
#define GOFF (BB*MS*DOF)  // offset of ws in out (30720)

typedef unsigned long long u64;

// ---------------- scratch (device globals: no allocs allowed) ----------------
__device__ float d_Mg[(size_t)BB*PG*DOF];            // 1.5 MB
__device__ float d_Mw[(size_t)BB*PW*JZP];            // ~161 MB
__device__ float d_xpre[BB*PG];
__device__ float d_ypre[BB*PW];
__device__ float d_xg[BB*PG];
__device__ float d_yw[BB*PW];
__device__ float d_gh[NL*BB*HG];
__device__ float d_gc[NL*BB*HG];
__device__ float d_wh[NL*BB*HW];
__device__ float d_wc[NL*BB*HW];
__device__ float d_gates_g[BB*4*HG];
__device__ float d_gates_w[BB*4*HW];
__device__ float d_bias_g[NL*4*HG];
__device__ float d_bias_w[NL*4*HW];

__device__ __forceinline__ float sigmoidf_(float x) { return 1.0f / (1.0f + expf(-x)); }

// ---------------- packed f32x2 helpers ---------------------------------------
__device__ __forceinline__ u64 pack2_(float x, float y) {
    u64 d; asm("mov.b64 %0, {%1, %2};" : "=l"(d) : "f"(x), "f"(y)); return d;
}
__device__ __forceinline__ u64 bdup_(float x) {
    u64 d; asm("mov.b64 %0, {%1, %1};" : "=l"(d) : "f"(x)); return d;
}
__device__ __forceinline__ float2 unpk_(u64 v) {
    float2 r; asm("mov.b64 {%0, %1}, %2;" : "=f"(r.x), "=f"(r.y) : "l"(v)); return r;
}
__device__ __forceinline__ u64 fma2_(u64 a, u64 b, u64 c) {
    u64 d; asm("fma.rn.f32x2 %0, %1, %2, %3;" : "=l"(d) : "l"(a), "l"(b), "l"(c)); return d;
}

// ---------------- init: zero states, combine biases, pad Mw, write t=0 -------
__global__ void init_kernel(const float* __restrict__ g0, const float* __restrict__ w0,
                            const float* __restrict__ lg_bih, const float* __restrict__ lg_bhh,
                            const float* __restrict__ lw_bih, const float* __restrict__ lw_bhh,
                            float* __restrict__ out)
{
    int tid = blockIdx.x * blockDim.x + threadIdx.x;
    int nt  = gridDim.x * blockDim.x;
    for (int i = tid; i < NL*BB*HG; i += nt) { d_gh[i] = 0.f; d_gc[i] = 0.f; }
    for (int i = tid; i < NL*BB*HW; i += nt) { d_wh[i] = 0.f; d_wc[i] = 0.f; }
    for (int i = tid; i < NL*4*HG; i += nt) d_bias_g[i] = lg_bih[i] + lg_bhh[i];
    for (int i = tid; i < NL*4*HW; i += nt) d_bias_w[i] = lw_bih[i] + lw_bhh[i];
    for (int i = tid; i < BB*PW; i += nt) {   // zero Mw padding columns
        d_Mw[(size_t)i*JZP + 306] = 0.f;
        d_Mw[(size_t)i*JZP + 307] = 0.f;
    }
    for (int i = tid; i < BB*DOF; i += nt) {
        int b = i / DOF, j = i % DOF;
        out[b*(MS*DOF) + j] = g0[i];
    }
    for (int i = tid; i < BB*WSZ; i += nt) {
        int b = i / WSZ, j = i % WSZ;
        out[GOFF + b*(MS*WSZ) + j] = w0[i];
    }
}

// ---------------- precompute M_g ---------------------------------------------
__global__ void pre_Mg_kernel(const float* __restrict__ ctx, const float* __restrict__ bgW)
{
    int o = blockIdx.x;                 // 0..PG-1
    __shared__ float w[CTXD*DOF];       // 12 KB
    for (int i = threadIdx.x; i < CTXD*DOF; i += blockDim.x)
        w[i] = bgW[(size_t)o*CTXD*DOF + i];
    __syncthreads();
    int b = threadIdx.x;                // blockDim = 256 = BB
    const float* cr = ctx + (size_t)b*CTXD;
    float acc[DOF];
    #pragma unroll
    for (int j = 0; j < DOF; j++) acc[j] = 0.f;
    for (int i = 0; i < CTXD; i++) {
        float c = cr[i];
        #pragma unroll
        for (int j = 0; j < DOF; j++) acc[j] += c * w[i*DOF + j];
    }
    #pragma unroll
    for (int j = 0; j < DOF; j++)
        d_Mg[((size_t)b*PG + o)*DOF + j] = acc[j];
}

// ---------------- dual-descriptor fp32x2 GEMM --------------------------------
// C = A(MxK) * B + A2(MxK2) * B2 (+bias) (tanh?).  transB=1: B is NxK (NT).
// transB=0: B is KxN (NN).  Batched (precompute) via strideB/strideC with z.
struct GDesc {
    const float *A, *B, *A2, *B2, *bias;
    float *C;
    int lda, ldb, lda2, ldb2, ldc;
    int M, N, K, K2;
    int transB, act, gx;
    long long strideB, strideC;
};

__global__ void __launch_bounds__(256)
gemm2_kernel(GDesc d0, GDesc d1, int z0)
{
    const int z = blockIdx.z;
    GDesc d = (z < z0) ? d0 : d1;
    const int bat = (z < z0) ? z : 0;
    if ((int)blockIdx.x >= d.gx || d.M == 0) return;

    const float* Bb0 = d.B + (long long)bat * d.strideB;
    float* C = d.C + (long long)bat * d.strideC;

    const int bm = blockIdx.y * 64;
    const int bn = blockIdx.x * 64;

    __shared__ __align__(16) float sA[2][16][68];
    __shared__ __align__(16) float sB[2][16][68];

    const int tid = threadIdx.x;
    const int tx = tid & 15;
    const int ty = tid >> 4;
    const int ar = tid >> 2;            // A/B-NT: row within tile (0..63)
    const int ac = (tid & 3) << 2;      // k offset (0,4,8,12)
    const int nkk = tid >> 4;           // B-NN: k row (0..15)
    const int nn4 = (tid & 15) << 2;    // B-NN: n offset (0..60)

    u64 acc[2][4];
    #pragma unroll
    for (int p = 0; p < 2; p++)
        #pragma unroll
        for (int j = 0; j < 4; j++) acc[p][j] = 0ull;

    #pragma unroll 1
    for (int pass = 0; pass < 2; ++pass) {
        const float* Ap = pass ? d.A2 : d.A;
        const float* Bp = pass ? d.B2 : Bb0;
        const int lA = pass ? d.lda2 : d.lda;
        const int lB = pass ? d.ldb2 : d.ldb;
        const int Kp = pass ? d.K2 : d.K;
        if (Ap == nullptr || Kp <= 0) continue;
        const int nc = Kp >> 4;

        // ---- load chunk 0 ----
        float4 pa = *(const float4*)(Ap + (size_t)(bm + ar)*lA + ac);
        float4 pb;
        if (d.transB) {
            int n = bn + ar;
            pb = (n < d.N) ? *(const float4*)(Bp + (size_t)n*lB + ac)
                           : make_float4(0.f, 0.f, 0.f, 0.f);
        } else {
            const float* src = Bp + (size_t)nkk*lB + bn + nn4;
            pb.x = (bn + nn4 + 0 < d.N) ? src[0] : 0.f;
            pb.y = (bn + nn4 + 1 < d.N) ? src[1] : 0.f;
            pb.z = (bn + nn4 + 2 < d.N) ? src[2] : 0.f;
            pb.w = (bn + nn4 + 3 < d.N) ? src[3] : 0.f;
        }
        // STS chunk 0 into buf 0
        sA[0][ac+0][ar] = pa.x; sA[0][ac+1][ar] = pa.y;
        sA[0][ac+2][ar] = pa.z; sA[0][ac+3][ar] = pa.w;
        if (d.transB) {
            sB[0][ac+0][ar] = pb.x; sB[0][ac+1][ar] = pb.y;
            sB[0][ac+2][ar] = pb.z; sB[0][ac+3][ar] = pb.w;
        } else {
            *(float4*)&sB[0][nkk][nn4] = pb;
        }
        __syncthreads();

        int buf = 0;
        #pragma unroll 1
        for (int c = 0; c < nc; ++c) {
            const bool more = (c + 1 < nc);
            float4 na, nb;
            if (more) {
                const int k0 = (c + 1) << 4;
                na = *(const float4*)(Ap + (size_t)(bm + ar)*lA + k0 + ac);
                if (d.transB) {
                    int n = bn + ar;
                    nb = (n < d.N) ? *(const float4*)(Bp + (size_t)n*lB + k0 + ac)
                                   : make_float4(0.f, 0.f, 0.f, 0.f);
                } else {
                    const float* src = Bp + (size_t)(k0 + nkk)*lB + bn + nn4;
                    nb.x = (bn + nn4 + 0 < d.N) ? src[0] : 0.f;
                    nb.y = (bn + nn4 + 1 < d.N) ? src[1] : 0.f;
                    nb.z = (bn + nn4 + 2 < d.N) ? src[2] : 0.f;
                    nb.w = (bn + nn4 + 3 < d.N) ? src[3] : 0.f;
                }
            }
            // ---- compute on buf ----
            #pragma unroll
            for (int kk = 0; kk < 16; kk++) {
                const float4 av = *(const float4*)&sA[buf][kk][ty*4];
                const float4 bv = *(const float4*)&sB[buf][kk][tx*4];
                const u64 a01 = pack2_(av.x, av.y);
                const u64 a23 = pack2_(av.z, av.w);
                u64 b;
                b = bdup_(bv.x); acc[0][0]=fma2_(a01,b,acc[0][0]); acc[1][0]=fma2_(a23,b,acc[1][0]);
                b = bdup_(bv.y); acc[0][1]=fma2_(a01,b,acc[0][1]); acc[1][1]=fma2_(a23,b,acc[1][1]);
                b = bdup_(bv.z); acc[0][2]=fma2_(a01,b,acc[0][2]); acc[1][2]=fma2_(a23,b,acc[1][2]);
                b = bdup_(bv.w); acc[0][3]=fma2_(a01,b,acc[0][3]); acc[1][3]=fma2_(a23,b,acc[1][3]);
            }
            if (more) {
                const int nbuf = buf ^ 1;
                sA[nbuf][ac+0][ar] = na.x; sA[nbuf][ac+1][ar] = na.y;
                sA[nbuf][ac+2][ar] = na.z; sA[nbuf][ac+3][ar] = na.w;
                if (d.transB) {
                    sB[nbuf][ac+0][ar] = nb.x; sB[nbuf][ac+1][ar] = nb.y;
                    sB[nbuf][ac+2][ar] = nb.z; sB[nbuf][ac+3][ar] = nb.w;
                } else {
                    *(float4*)&sB[nbuf][nkk][nn4] = nb;
                }
            }
            __syncthreads();
            buf ^= 1;
        }
    }

    // ---- epilogue ----
    const int n0 = bn + tx*4;
    float4 bb = make_float4(0.f, 0.f, 0.f, 0.f);
    if (d.bias) {
        if (n0 + 0 < d.N) bb.x = d.bias[n0 + 0];
        if (n0 + 1 < d.N) bb.y = d.bias[n0 + 1];
        if (n0 + 2 < d.N) bb.z = d.bias[n0 + 2];
        if (n0 + 3 < d.N) bb.w = d.bias[n0 + 3];
    }
    const bool vec = ((d.ldc & 3) == 0) && ((((size_t)C) & 15) == 0) && (bn + 64 <= d.N);
    #pragma unroll
    for (int p = 0; p < 2; p++) {
        const float2 v0 = unpk_(acc[p][0]);
        const float2 v1 = unpk_(acc[p][1]);
        const float2 v2 = unpk_(acc[p][2]);
        const float2 v3 = unpk_(acc[p][3]);
        float4 r0 = make_float4(v0.x + bb.x, v1.x + bb.y, v2.x + bb.z, v3.x + bb.w);
        float4 r1 = make_float4(v0.y + bb.x, v1.y + bb.y, v2.y + bb.z, v3.y + bb.w);
        if (d.act) {
            r0.x = tanhf(r0.x); r0.y = tanhf(r0.y); r0.z = tanhf(r0.z); r0.w = tanhf(r0.w);
            r1.x = tanhf(r1.x); r1.y = tanhf(r1.y); r1.z = tanhf(r1.z); r1.w = tanhf(r1.w);
        }
        const int m = bm + ty*4 + 2*p;
        if (vec) {
            *(float4*)(C + (size_t)m*d.ldc + n0) = r0;
            *(float4*)(C + (size_t)(m+1)*d.ldc + n0) = r1;
        } else {
            const float rr0[4] = {r0.x, r0.y, r0.z, r0.w};
            const float rr1[4] = {r1.x, r1.y, r1.z, r1.w};
            #pragma unroll
            for (int j = 0; j < 4; j++) {
                if (n0 + j < d.N) {
                    C[(size_t)m*d.ldc + n0 + j] = rr0[j];
                    C[(size_t)(m+1)*d.ldc + n0 + j] = rr1[j];
                }
            }
        }
    }
}

// ---------------- per-step bilinear matvecs (float4, padded rows) ------------
__global__ void bilinear_kernel(int t, const float* __restrict__ bg_b,
                                const float* __restrict__ bw_b,
                                const float* __restrict__ out)
{
    const int b = blockIdx.x;
    __shared__ __align__(16) float zs[JZP];
    const int tid = threadIdx.x;
    for (int i = tid; i < JZP; i += blockDim.x) {
        float v = 0.f;
        if (i < DOF)            v = out[(size_t)b*MS*DOF + t*DOF + i];
        else if (i - DOF < WSZ) v = out[GOFF + (size_t)b*MS*WSZ + t*WSZ + (i - DOF)];
        zs[i] = v;
    }
    __syncthreads();
    if (blockIdx.y < PW/8) {
        const int o = blockIdx.y * 8 + (tid >> 5);
        const int lane = tid & 31;
        const float4* mw = (const float4*)(d_Mw + ((size_t)b*PW + o)*JZP);
        const float4* z4 = (const float4*)zs;
        float s = 0.f;
        for (int j4 = lane; j4 < JZP/4; j4 += 32) {
            const float4 m = mw[j4];
            const float4 z = z4[j4];
            s += m.x*z.x + m.y*z.y + m.z*z.z + m.w*z.w;
        }
        #pragma unroll
        for (int off = 16; off; off >>= 1) s += __shfl_down_sync(0xffffffffu, s, off);
        if (lane == 0) d_ypre[b*PW + o] = s + bw_b[o];
    } else {
        // x branch: tid is o (256 outputs, 6-elem dot)
        const float* mg = d_Mg + ((size_t)b*PG + tid)*DOF;
        float s = bg_b[tid];
        #pragma unroll
        for (int j = 0; j < DOF; j++) s += mg[j] * zs[j];
        d_xpre[b*PG + tid] = s;
    }
}

// ---------------- merged LSTM pointwise (g-chain + w-chain) ------------------
__global__ void lstm_point2_kernel(const float* __restrict__ gg, const float* __restrict__ gw,
                                   float* __restrict__ hgp, float* __restrict__ cgp,
                                   float* __restrict__ hwp, float* __restrict__ cwp)
{
    int idx = blockIdx.x * blockDim.x + threadIdx.x;
    const float* gates; float* h; float* c; int H;
    if (idx < BB*HG) { gates = gg; h = hgp; c = cgp; H = HG; }
    else {
        idx -= BB*HG;
        if (idx >= BB*HW) return;
        gates = gw; h = hwp; c = cwp; H = HW;
    }
    const int b = idx / H, j = idx % H;
    const float* g = gates + (size_t)b*4*H;
    const float ig = sigmoidf_(g[j]);
    const float fg = sigmoidf_(g[H + j]);
    const float gv = tanhf(g[2*H + j]);
    const float og = sigmoidf_(g[3*H + j]);
    const float cn = fg * c[idx] + ig * gv;
    c[idx] = cn;
    h[idx] = og * tanhf(cn);
}

// ---------------- host helpers -----------------------------------------------
static inline GDesc mk(const float* A, int lda, const float* B, int ldb, int transB,
                       const float* A2, int lda2, const float* B2, int ldb2,
                       const float* bias, float* C, int ldc,
                       int M, int N, int K, int K2, int act,
                       long long sB = 0, long long sC = 0)
{
    GDesc d;
    d.A = A; d.B = B; d.A2 = A2; d.B2 = B2; d.bias = bias; d.C = C;
    d.lda = lda; d.ldb = ldb; d.lda2 = lda2; d.ldb2 = ldb2; d.ldc = ldc;
    d.M = M; d.N = N; d.K = K; d.K2 = K2;
    d.transB = transB; d.act = act; d.gx = (N + 63) / 64;
    d.strideB = sB; d.strideC = sC;
    return d;
}

extern "C" void kernel_launch(void* const* d_in, const int* in_sizes, int n_in,
                              void* d_out, int out_size)
{
    const float* ctx    = (const float*)d_in[0];
    const float* goal0  = (const float*)d_in[1];
    const float* w0     = (const float*)d_in[2];
    const float* bg_W   = (const float*)d_in[3];
    const float* bg_b   = (const float*)d_in[4];
    const float* bw_W   = (const float*)d_in[5];
    const float* bw_b   = (const float*)d_in[6];
    const float* fcg_W  = (const float*)d_in[7];
    const float* fcg_b  = (const float*)d_in[8];
    const float* fcw_W  = (const float*)d_in[9];
    const float* fcw_b  = (const float*)d_in[10];
    const float* lg_Wih = (const float*)d_in[11];
    const float* lg_Whh = (const float*)d_in[12];
    const float* lg_bih = (const float*)d_in[13];
    const float* lg_bhh = (const float*)d_in[14];
    const float* lw_Wih = (const float*)d_in[15];
    const float* lw_Whh = (const float*)d_in[16];
    const float* lw_bih = (const float*)d_in[17];
    const float* lw_bhh = (const float*)d_in[18];
    const float* og_W   = (const float*)d_in[19];
    const float* og_b   = (const float*)d_in[20];
    const float* ow_W   = (const float*)d_in[21];
    const float* ow_b   = (const float*)d_in[22];
    float* out = (float*)d_out;

    float *Mw, *xpre, *ypre, *xg, *yw, *gh, *gc, *wh, *wc, *ggb, *gwb, *bias_g, *bias_w;
    cudaGetSymbolAddress((void**)&Mw, d_Mw);
    cudaGetSymbolAddress((void**)&xpre, d_xpre);
    cudaGetSymbolAddress((void**)&ypre, d_ypre);
    cudaGetSymbolAddress((void**)&xg, d_xg);
    cudaGetSymbolAddress((void**)&yw, d_yw);
    cudaGetSymbolAddress((void**)&gh, d_gh);
    cudaGetSymbolAddress((void**)&gc, d_gc);
    cudaGetSymbolAddress((void**)&wh, d_wh);
    cudaGetSymbolAddress((void**)&wc, d_wc);
    cudaGetSymbolAddress((void**)&ggb, d_gates_g);
    cudaGetSymbolAddress((void**)&gwb, d_gates_w);
    cudaGetSymbolAddress((void**)&bias_g, d_bias_g);
    cudaGetSymbolAddress((void**)&bias_w, d_bias_w);

    GDesc empty = {};
    empty.M = 0; empty.gx = 0;

    // --- init + precompute (context is step-invariant) ---
    init_kernel<<<256, 256>>>(goal0, w0, lg_bih, lg_bhh, lw_bih, lw_bhh, out);
    pre_Mg_kernel<<<PG, 256>>>(ctx, bg_W);

    // M_w[b,o,jp] = sum_i ctx[b,i] * bw_W[o,i,j] : batched over o (z = o)
    {
        GDesc dmw = mk(ctx, CTXD, bw_W, JZ, /*transB=*/0,
                       nullptr, 0, nullptr, 0, nullptr,
                       Mw, PW*JZP, BB, JZ, CTXD, 0, 0,
                       (long long)CTXD*JZ, (long long)JZP);
        gemm2_kernel<<<dim3(dmw.gx, BB/64, PW), 256>>>(dmw, empty, PW);
    }

    for (int t = 0; t < STEPS; ++t) {
        // 1. bilinear matvecs
        bilinear_kernel<<<dim3(BB, PW/8 + 1), 256>>>(t, bg_b, bw_b, out);

        // 2. fc + tanh (both branches, one launch)
        {
            GDesc dg = mk(xpre, PG, fcg_W, PG, 1, nullptr, 0, nullptr, 0,
                          fcg_b, xg, PG, BB, PG, PG, 0, 1);
            GDesc dw = mk(ypre, PW, fcw_W, PW, 1, nullptr, 0, nullptr, 0,
                          fcw_b, yw, PW, BB, PW, PW, 0, 1);
            int gx = dg.gx > dw.gx ? dg.gx : dw.gx;
            gemm2_kernel<<<dim3(gx, BB/64, 2), 256>>>(dg, dw, 1);
        }

        // 3+4. LSTM layers (g-chain and w-chain gate GEMMs merged per layer)
        for (int l = 0; l < NL; ++l) {
            const float* ing = (l == 0) ? xg : gh;
            const float* inw = (l == 0) ? yw : wh;
            GDesc dg = mk(ing, (l == 0) ? PG : HG,
                          lg_Wih + (size_t)l*4*HG*PG, (l == 0) ? PG : HG, 1,
                          gh + (size_t)l*BB*HG, HG,
                          lg_Whh + (size_t)l*4*HG*HG, HG,
                          bias_g + l*4*HG, ggb, 4*HG,
                          BB, 4*HG, (l == 0) ? PG : HG, HG, 0);
            GDesc dw = mk(inw, (l == 0) ? PW : HW,
                          lw_Wih + (size_t)l*4*HW*PW, (l == 0) ? PW : HW, 1,
                          wh + (size_t)l*BB*HW, HW,
                          lw_Whh + (size_t)l*4*HW*HW, HW,
                          bias_w + l*4*HW, gwb, 4*HW,
                          BB, 4*HW, (l == 0) ? PW : HW, HW, 0);
            int gx = dg.gx > dw.gx ? dg.gx : dw.gx;
            gemm2_kernel<<<dim3(gx, BB/64, 2), 256>>>(dg, dw, 1);
            lstm_point2_kernel<<<(BB*HG + BB*HW + 255)/256, 256>>>(
                ggb, gwb,
                gh + (size_t)l*BB*HG, gc + (size_t)l*BB*HG,
                wh + (size_t)l*BB*HW, wc + (size_t)l*BB*HW);
        }

        // 5. output projections (merged), written into out rows t+1
        {
            GDesc dg = mk(gh + (size_t)1*BB*HG, HG, og_W, HG, 1, nullptr, 0, nullptr, 0,
                          og_b, out + (t + 1)*DOF, MS*DOF, BB, DOF, HG, 0, 0);
            GDesc dw = mk(wh + (size_t)1*BB*HW, HW, ow_W, HW, 1, nullptr, 0, nullptr, 0,
                          ow_b, out + GOFF + (t + 1)*WSZ, MS*WSZ, BB, WSZ, HW, 0, 0);
            int gx = dg.gx > dw.gx ? dg.gx : dw.gx;
            gemm2_kernel<<<dim3(gx, BB/64, 2), 256>>>(dg, dw, 1);
        }
    }
}